// round 14
// baseline (speedup 1.0000x reference)
#include <cuda_runtime.h>
#include <cstdint>

// Problem constants
constexpr int B_  = 4;
constexpr int T_  = 2048;
constexpr int D_  = 1024;
constexpr int H_  = 16;
constexpr int HD_ = 64;
constexpr int MROWS = B_ * T_;   // 8192
constexpr int KDIM  = D_;        // 1024

// Scratch (device globals: allocation-free)
__device__ float g_q[(size_t)B_ * H_ * T_ * HD_];
__device__ float g_k[(size_t)B_ * H_ * T_ * HD_];
__device__ float g_v[(size_t)B_ * H_ * T_ * HD_];
__device__ float g_o[(size_t)MROWS * D_];

// ---------------------------------------------------------------------------
// tf32 helpers (mma.sync path — plain sm_103 PTX target)
// ---------------------------------------------------------------------------
__device__ __forceinline__ uint32_t f2tf32(float f) {
    uint32_t u;
    asm("cvt.rna.tf32.f32 %0, %1;" : "=r"(u) : "f"(f));
    return u;
}

__device__ __forceinline__ void mma_tf32(float c[4], const uint32_t a[4],
                                         const uint32_t b[2]) {
    asm volatile(
        "mma.sync.aligned.m16n8k8.row.col.f32.tf32.tf32.f32 "
        "{%0,%1,%2,%3}, {%4,%5,%6,%7}, {%8,%9}, {%0,%1,%2,%3};"
        : "+f"(c[0]), "+f"(c[1]), "+f"(c[2]), "+f"(c[3])
        : "r"(a[0]), "r"(a[1]), "r"(a[2]), "r"(a[3]), "r"(b[0]), "r"(b[1]));
}

// ===========================================================================
// tf32 tensor-core GEMM body (structure unchanged from R11; now shared by a
// merged-QKV wrapper (grid.z selects W/bias) and the output-proj wrapper).
// ===========================================================================
constexpr int BKF = 32;
constexpr int LDS_S = 36;
constexpr int GBUFW = 2 * 128 * LDS_S;            // As+Bs words per buffer
constexpr int GEMM_SMEM = 2 * GBUFW * 4;          // 73728 B

__device__ __forceinline__ void
gemm_body(const float* __restrict__ A,
          const float* __restrict__ W,
          const float* __restrict__ bias,
          float* __restrict__ Yext,
          int mode)
{
    extern __shared__ uint32_t gsm[];

    float* Y = (mode == 0) ? g_q : (mode == 1) ? g_k : (mode == 2) ? g_v : Yext;

    const int bn0 = blockIdx.x * 128;
    const int bm0 = blockIdx.y * 128;

    const int tid  = threadIdx.x;
    const int lane = tid & 31;
    const int wid  = tid >> 5;
    const int g    = lane >> 2;
    const int tg   = lane & 3;
    const int wm   = (wid >> 2) * 64;
    const int wn   = (wid & 3) * 32;

    float acc[4][4][4];
    #pragma unroll
    for (int i = 0; i < 4; i++)
        #pragma unroll
        for (int j = 0; j < 4; j++)
            #pragma unroll
            for (int r = 0; r < 4; r++) acc[i][j][r] = 0.f;

    const int lr4 = tid >> 3;
    const int lc4 = tid & 7;

    const float4* gA = (const float4*)(A + (size_t)(bm0 + lr4) * KDIM) + lc4;
    const float4* gB = (const float4*)(W + (size_t)(bn0 + lr4) * KDIM) + lc4;
    const int rowStep4 = 32 * (KDIM / 4);

    float4 ra[4], rb[4];

    auto stage = [&](int p) {
        uint32_t* As = gsm + p * GBUFW;
        uint32_t* Bs = As + 128 * LDS_S;
        #pragma unroll
        for (int i = 0; i < 4; i++) {
            const int s = (lr4 + i * 32) * LDS_S + lc4 * 4;
            As[s + 0] = f2tf32(ra[i].x); As[s + 1] = f2tf32(ra[i].y);
            As[s + 2] = f2tf32(ra[i].z); As[s + 3] = f2tf32(ra[i].w);
            Bs[s + 0] = f2tf32(rb[i].x); Bs[s + 1] = f2tf32(rb[i].y);
            Bs[s + 2] = f2tf32(rb[i].z); Bs[s + 3] = f2tf32(rb[i].w);
        }
    };
    auto fetch = [&](int kc) {
        const int koff = kc * (BKF / 4);
        #pragma unroll
        for (int i = 0; i < 4; i++) {
            ra[i] = gA[(size_t)i * rowStep4 + koff];
            rb[i] = gB[(size_t)i * rowStep4 + koff];
        }
    };

    const int NK = KDIM / BKF;   // 32

    fetch(0);
    stage(0);
    fetch(1);

    for (int kc = 0; kc < NK; kc++) {
        __syncthreads();
        if (kc + 1 < NK) {
            stage((kc + 1) & 1);
            if (kc + 2 < NK) fetch(kc + 2);
        }

        const uint32_t* As = gsm + (kc & 1) * GBUFW;
        const uint32_t* Bs = As + 128 * LDS_S;

        #pragma unroll
        for (int s = 0; s < 4; s++) {
            uint32_t af[4][4];
            #pragma unroll
            for (int i = 0; i < 4; i++) {
                const int base = (wm + i * 16 + g) * LDS_S + s * 8 + tg;
                af[i][0] = As[base];
                af[i][1] = As[base + 8 * LDS_S];
                af[i][2] = As[base + 4];
                af[i][3] = As[base + 8 * LDS_S + 4];
            }
            uint32_t bf[4][2];
            #pragma unroll
            for (int j = 0; j < 4; j++) {
                const int base = (wn + j * 8 + g) * LDS_S + s * 8 + tg;
                bf[j][0] = Bs[base];
                bf[j][1] = Bs[base + 4];
            }
            #pragma unroll
            for (int i = 0; i < 4; i++)
                #pragma unroll
                for (int j = 0; j < 4; j++)
                    mma_tf32(acc[i][j], af[i], bf[j]);
        }
    }

    #pragma unroll
    for (int j = 0; j < 4; j++) {
        const int n = bn0 + wn + j * 8 + 2 * tg;
        const float bx = bias[n], by = bias[n + 1];
        #pragma unroll
        for (int i = 0; i < 4; i++) {
            const int m0 = bm0 + wm + i * 16 + g;
            float2 v0 = make_float2(acc[i][j][0] + bx, acc[i][j][1] + by);
            float2 v1 = make_float2(acc[i][j][2] + bx, acc[i][j][3] + by);
            if (mode < 3) {
                const int h = n >> 6, hd = n & (HD_ - 1);
                const int bb0 = m0 >> 11, t0 = m0 & (T_ - 1);
                const int m1 = m0 + 8;
                const int bb1 = m1 >> 11, t1 = m1 & (T_ - 1);
                *(float2*)&Y[(((size_t)bb0 * H_ + h) * T_ + t0) * HD_ + hd] = v0;
                *(float2*)&Y[(((size_t)bb1 * H_ + h) * T_ + t1) * HD_ + hd] = v1;
            } else {
                *(float2*)&Y[(size_t)m0 * D_ + n] = v0;
                *(float2*)&Y[(size_t)(m0 + 8) * D_ + n] = v1;
            }
        }
    }
}

// Merged QKV launch: blockIdx.z in {0,1,2} selects the projection.
__global__ void __launch_bounds__(256)
gemm_qkv(const float* __restrict__ x,
         const float* __restrict__ Wq, const float* __restrict__ bq,
         const float* __restrict__ Wk, const float* __restrict__ bk,
         const float* __restrict__ Wv, const float* __restrict__ bv)
{
    const int m = blockIdx.z;
    const float* W = (m == 0) ? Wq : (m == 1) ? Wk : Wv;
    const float* b = (m == 0) ? bq : (m == 1) ? bk : bv;
    gemm_body(x, W, b, nullptr, m);
}

__global__ void __launch_bounds__(256)
gemm_out(const float* __restrict__ Wo, const float* __restrict__ bo,
         float* __restrict__ out)
{
    gemm_body(g_o, Wo, bo, out, 3);
}

// ===========================================================================
// Tensor-core flash attention v5 (tf32 mma.sync).
// R14: CTA shrunk to 128 threads / FBr=64 (per-warp work identical) so
// 3 CTAs fit per SM (regs 170*128*3 <= 64K, smem 3*71.7KB <= 228KB) ->
// 12 warps/SM instead of 8. Persistent K/V register prefetch dropped
// (R7: worth ~1%); staging is inline LDG->STS, double-buffered. Grid
// (qtile, bh) so concurrent CTAs share one bh's K/V in L2.
// ===========================================================================
constexpr int FBr = 64, FBc = 64;
constexpr int FST_K = 72;                        // Khi row stride (words)
constexpr int FST_V = 68;                        // Vs  row stride (words)
constexpr int KHI_WORDS = 64 * FST_K;            // 4608
constexpr int BUF_WORDS = KHI_WORDS + 64 * FST_V; // 8960 per buffer
constexpr int QST = 65;                          // Q staging stride (buf 1)
constexpr int FLASH_SMEM = 2 * BUF_WORDS * 4;    // 71680 B
constexpr int FTHREADS = 128;

__device__ __forceinline__ int permc(int c) {    // permute col within k8 step
    return ((c & 3) << 1) | (c >> 2);
}

__global__ void __launch_bounds__(FTHREADS, 3)
flash_tc()
{
    extern __shared__ uint32_t smw[];

    const int bh = blockIdx.y;
    const int q0 = blockIdx.x * FBr;
    const float* Qg = g_q + (size_t)bh * T_ * HD_;
    const float* Kg = g_k + (size_t)bh * T_ * HD_;
    const float* Vg = g_v + (size_t)bh * T_ * HD_;

    const int tid = threadIdx.x, lane = tid & 31, wid = tid >> 5;
    const int g = lane >> 2, tg = lane & 3;
    const int wr = wid * 16;                      // wid 0..3 -> rows 0..63

    // K/V staging mapping: rows rr+8i (i=0..7), float4 column cc.
    const int rr = tid >> 4;                      // 0..7
    const int cc = tid & 15;
    const float4* K4 = (const float4*)Kg + cc;
    const float4* V4 = (const float4*)Vg + cc;

    auto stageKV = [&](int bufIdx, int tile) {
        uint32_t* Khi = smw + bufIdx * BUF_WORDS;
        uint32_t* Vs  = Khi + KHI_WORDS;
        const size_t base = (size_t)tile * 64;
        const int dbase = cc * 4;
        #pragma unroll
        for (int i = 0; i < 8; i++) {
            const int r = rr + 8 * i;
            const float4 kv = K4[(base + r) * 16];
            const float kf[4] = {kv.x, kv.y, kv.z, kv.w};
            #pragma unroll
            for (int u = 0; u < 4; u++) {
                const int d = dbase + u;
                Khi[r * FST_K + (d & ~7) + permc(d & 7)] = f2tf32(kf[u]);
            }
        }
        #pragma unroll
        for (int i = 0; i < 8; i++) {
            const int r = rr + 8 * i;
            const float4 vv = V4[(base + r) * 16];
            uint4 vw;
            vw.x = f2tf32(vv.x); vw.y = f2tf32(vv.y);
            vw.z = f2tf32(vv.z); vw.w = f2tf32(vv.w);
            *(uint4*)&Vs[r * FST_V + dbase] = vw;
        }
    };

    // ---- Stage Q (pre-scaled) into buffer-1 region ----
    float* Qst = (float*)(smw + BUF_WORDS);
    #pragma unroll
    for (int i = 0; i < 8; i++) {                 // 64 rows x 16 f4
        const int idx = tid + i * FTHREADS;
        const int r = idx >> 4, qc4 = idx & 15;
        float4 q = *(const float4*)(Qg + (size_t)(q0 + r) * HD_ + qc4 * 4);
        float* d = Qst + r * QST + qc4 * 4;
        d[0] = q.x * 0.125f; d[1] = q.y * 0.125f;
        d[2] = q.z * 0.125f; d[3] = q.w * 0.125f;
    }
    __syncthreads();

    // ---- Extract Q A-fragments (single tf32) ----
    uint32_t qh[8][4];
    #pragma unroll
    for (int s = 0; s < 8; s++) {
        qh[s][0] = f2tf32(Qst[(wr + g)     * QST + s * 8 + tg]);
        qh[s][1] = f2tf32(Qst[(wr + g + 8) * QST + s * 8 + tg]);
        qh[s][2] = f2tf32(Qst[(wr + g)     * QST + s * 8 + tg + 4]);
        qh[s][3] = f2tf32(Qst[(wr + g + 8) * QST + s * 8 + tg + 4]);
    }

    // ---- Stage tile 0 into buffer 0 (does not touch Q region) ----
    stageKV(0, 0);

    float o[8][4];
    #pragma unroll
    for (int j = 0; j < 8; j++)
        #pragma unroll
        for (int r = 0; r < 4; r++) o[j][r] = 0.f;
    float m0 = -1e30f, m1 = -1e30f, l0 = 0.f, l1 = 0.f;

    constexpr int NT = T_ / FBc;                  // 32
    for (int it = 0; it < NT; it++) {
        // Orders: (a) all Q reads / prev-iter reads of buf[(it+1)&1] done
        // before restaging it; (b) staging of buf[it&1] visible to all.
        __syncthreads();

        if (it + 1 < NT) stageKV((it + 1) & 1, it + 1);

        const uint32_t* buf = smw + (it & 1) * BUF_WORDS;
        const uint32_t* Khi = buf;
        const uint32_t* Vs  = buf + KHI_WORDS;

        // ---- S = Q @ K^T (single tf32) ----
        float sacc[8][4];
        #pragma unroll
        for (int j = 0; j < 8; j++)
            #pragma unroll
            for (int r = 0; r < 4; r++) sacc[j][r] = 0.f;

        #pragma unroll
        for (int s = 0; s < 8; s++) {
            #pragma unroll
            for (int jt = 0; jt < 8; jt++) {
                const uint2 kh2 = *(const uint2*)&Khi[(jt * 8 + g) * FST_K + s * 8 + 2 * tg];
                const uint32_t bhh[2] = {kh2.x, kh2.y};
                mma_tf32(sacc[jt], qh[s], bhh);
            }
        }

        // ---- Online softmax (rows g and g+8); e's stay in sacc regs ----
        float mx0 = -1e30f, mx1 = -1e30f;
        #pragma unroll
        for (int jt = 0; jt < 8; jt++) {
            mx0 = fmaxf(mx0, fmaxf(sacc[jt][0], sacc[jt][1]));
            mx1 = fmaxf(mx1, fmaxf(sacc[jt][2], sacc[jt][3]));
        }
        mx0 = fmaxf(mx0, __shfl_xor_sync(0xffffffffu, mx0, 1));
        mx0 = fmaxf(mx0, __shfl_xor_sync(0xffffffffu, mx0, 2));
        mx1 = fmaxf(mx1, __shfl_xor_sync(0xffffffffu, mx1, 1));
        mx1 = fmaxf(mx1, __shfl_xor_sync(0xffffffffu, mx1, 2));

        const float mn0 = fmaxf(m0, mx0), mn1 = fmaxf(m1, mx1);
        const float a0 = __expf(m0 - mn0), a1 = __expf(m1 - mn1);

        float rs0 = 0.f, rs1 = 0.f;
        #pragma unroll
        for (int jt = 0; jt < 8; jt++) {
            sacc[jt][0] = __expf(sacc[jt][0] - mn0);
            sacc[jt][1] = __expf(sacc[jt][1] - mn0);
            sacc[jt][2] = __expf(sacc[jt][2] - mn1);
            sacc[jt][3] = __expf(sacc[jt][3] - mn1);
            rs0 += sacc[jt][0] + sacc[jt][1];
            rs1 += sacc[jt][2] + sacc[jt][3];
        }
        rs0 += __shfl_xor_sync(0xffffffffu, rs0, 1);
        rs0 += __shfl_xor_sync(0xffffffffu, rs0, 2);
        rs1 += __shfl_xor_sync(0xffffffffu, rs1, 1);
        rs1 += __shfl_xor_sync(0xffffffffu, rs1, 2);

        l0 = l0 * a0 + rs0;
        l1 = l1 * a1 + rs1;
        m0 = mn0; m1 = mn1;
        #pragma unroll
        for (int jt = 0; jt < 8; jt++) {
            o[jt][0] *= a0; o[jt][1] *= a0;
            o[jt][2] *= a1; o[jt][3] *= a1;
        }

        // ---- O += P @ V : P direct from registers (permuted key slots) ----
        #pragma unroll
        for (int jt = 0; jt < 8; jt++) {
            const uint32_t pa[4] = {f2tf32(sacc[jt][0]), f2tf32(sacc[jt][2]),
                                    f2tf32(sacc[jt][1]), f2tf32(sacc[jt][3])};
            const uint32_t* v0row = &Vs[(jt * 8 + 2 * tg)     * FST_V + g];
            const uint32_t* v1row = &Vs[(jt * 8 + 2 * tg + 1) * FST_V + g];
            #pragma unroll
            for (int dt = 0; dt < 8; dt++) {
                const uint32_t vb[2] = {v0row[dt * 8], v1row[dt * 8]};
                mma_tf32(o[dt], pa, vb);
            }
        }
    }

    // ---- Epilogue: normalize, write to [B, T, H*HD] ----
    const float i0 = 1.0f / l0, i1 = 1.0f / l1;
    const int bb = bh >> 4, h = bh & 15;
    const int row0 = q0 + wr + g, row1 = row0 + 8;
    #pragma unroll
    for (int dt = 0; dt < 8; dt++) {
        const int dcol = h * HD_ + dt * 8 + 2 * tg;
        *(float2*)&g_o[((size_t)bb * T_ + row0) * D_ + dcol] =
            make_float2(o[dt][0] * i0, o[dt][1] * i0);
        *(float2*)&g_o[((size_t)bb * T_ + row1) * D_ + dcol] =
            make_float2(o[dt][2] * i1, o[dt][3] * i1);
    }
}

// ---------------------------------------------------------------------------
extern "C" void kernel_launch(void* const* d_in, const int* in_sizes, int n_in,
                              void* d_out, int out_size)
{
    const float* x  = (const float*)d_in[0];
    const float* Wq = (const float*)d_in[1];
    const float* bq = (const float*)d_in[2];
    const float* Wk = (const float*)d_in[3];
    const float* bk = (const float*)d_in[4];
    const float* Wv = (const float*)d_in[5];
    const float* bv = (const float*)d_in[6];
    const float* Wo = (const float*)d_in[7];
    const float* bo = (const float*)d_in[8];
    float* out = (float*)d_out;

    cudaFuncSetAttribute(gemm_qkv, cudaFuncAttributeMaxDynamicSharedMemorySize,
                         GEMM_SMEM);
    cudaFuncSetAttribute(gemm_out, cudaFuncAttributeMaxDynamicSharedMemorySize,
                         GEMM_SMEM);
    cudaFuncSetAttribute(flash_tc, cudaFuncAttributeMaxDynamicSharedMemorySize,
                         FLASH_SMEM);

    dim3 gq(D_ / 128, MROWS / 128, 3);       // (8, 64, 3) merged QKV
    gemm_qkv<<<gq, 256, GEMM_SMEM>>>(x, Wq, bq, Wk, bk, Wv, bv);

    dim3 attn_grid(T_ / FBr, B_ * H_);       // (32, 64): x=qtile, y=bh
    flash_tc<<<attn_grid, FTHREADS, FLASH_SMEM>>>();

    dim3 gg(D_ / 128, MROWS / 128);          // (8, 64)
    gemm_out<<<gg, 256, GEMM_SMEM>>>(Wo, bo, out);
}

// round 16
// speedup vs baseline: 1.0905x; 1.0905x over previous
#include <cuda_runtime.h>
#include <cstdint>

// Problem constants
constexpr int B_  = 4;
constexpr int T_  = 2048;
constexpr int D_  = 1024;
constexpr int H_  = 16;
constexpr int HD_ = 64;
constexpr int MROWS = B_ * T_;   // 8192
constexpr int KDIM  = D_;        // 1024

// Scratch (device globals: allocation-free)
__device__ float g_q[(size_t)B_ * H_ * T_ * HD_];
__device__ float g_k[(size_t)B_ * H_ * T_ * HD_];
__device__ float g_v[(size_t)B_ * H_ * T_ * HD_];
__device__ float g_o[(size_t)MROWS * D_];

// ---------------------------------------------------------------------------
// tf32 helpers (mma.sync path — plain sm_103 PTX target)
// ---------------------------------------------------------------------------
__device__ __forceinline__ uint32_t f2tf32(float f) {
    uint32_t u;
    asm("cvt.rna.tf32.f32 %0, %1;" : "=r"(u) : "f"(f));
    return u;
}

__device__ __forceinline__ void mma_tf32(float c[4], const uint32_t a[4],
                                         const uint32_t b[2]) {
    asm volatile(
        "mma.sync.aligned.m16n8k8.row.col.f32.tf32.tf32.f32 "
        "{%0,%1,%2,%3}, {%4,%5,%6,%7}, {%8,%9}, {%0,%1,%2,%3};"
        : "+f"(c[0]), "+f"(c[1]), "+f"(c[2]), "+f"(c[3])
        : "r"(a[0]), "r"(a[1]), "r"(a[2]), "r"(a[3]), "r"(b[0]), "r"(b[1]));
}

// ===========================================================================
// tf32 tensor-core GEMM body (unchanged). Merged-QKV wrapper kept (R14 win:
// 3 GEMMs in one 1536-CTA launch = 347us vs ~390 split).
// ===========================================================================
constexpr int BKF = 32;
constexpr int LDS_S = 36;
constexpr int GBUFW = 2 * 128 * LDS_S;            // As+Bs words per buffer
constexpr int GEMM_SMEM = 2 * GBUFW * 4;          // 73728 B

__device__ __forceinline__ void
gemm_body(const float* __restrict__ A,
          const float* __restrict__ W,
          const float* __restrict__ bias,
          float* __restrict__ Yext,
          int mode)
{
    extern __shared__ uint32_t gsm[];

    float* Y = (mode == 0) ? g_q : (mode == 1) ? g_k : (mode == 2) ? g_v : Yext;

    const int bn0 = blockIdx.x * 128;
    const int bm0 = blockIdx.y * 128;

    const int tid  = threadIdx.x;
    const int lane = tid & 31;
    const int wid  = tid >> 5;
    const int g    = lane >> 2;
    const int tg   = lane & 3;
    const int wm   = (wid >> 2) * 64;
    const int wn   = (wid & 3) * 32;

    float acc[4][4][4];
    #pragma unroll
    for (int i = 0; i < 4; i++)
        #pragma unroll
        for (int j = 0; j < 4; j++)
            #pragma unroll
            for (int r = 0; r < 4; r++) acc[i][j][r] = 0.f;

    const int lr4 = tid >> 3;
    const int lc4 = tid & 7;

    const float4* gA = (const float4*)(A + (size_t)(bm0 + lr4) * KDIM) + lc4;
    const float4* gB = (const float4*)(W + (size_t)(bn0 + lr4) * KDIM) + lc4;
    const int rowStep4 = 32 * (KDIM / 4);

    float4 ra[4], rb[4];

    auto stage = [&](int p) {
        uint32_t* As = gsm + p * GBUFW;
        uint32_t* Bs = As + 128 * LDS_S;
        #pragma unroll
        for (int i = 0; i < 4; i++) {
            const int s = (lr4 + i * 32) * LDS_S + lc4 * 4;
            As[s + 0] = f2tf32(ra[i].x); As[s + 1] = f2tf32(ra[i].y);
            As[s + 2] = f2tf32(ra[i].z); As[s + 3] = f2tf32(ra[i].w);
            Bs[s + 0] = f2tf32(rb[i].x); Bs[s + 1] = f2tf32(rb[i].y);
            Bs[s + 2] = f2tf32(rb[i].z); Bs[s + 3] = f2tf32(rb[i].w);
        }
    };
    auto fetch = [&](int kc) {
        const int koff = kc * (BKF / 4);
        #pragma unroll
        for (int i = 0; i < 4; i++) {
            ra[i] = gA[(size_t)i * rowStep4 + koff];
            rb[i] = gB[(size_t)i * rowStep4 + koff];
        }
    };

    const int NK = KDIM / BKF;   // 32

    fetch(0);
    stage(0);
    fetch(1);

    for (int kc = 0; kc < NK; kc++) {
        __syncthreads();
        if (kc + 1 < NK) {
            stage((kc + 1) & 1);
            if (kc + 2 < NK) fetch(kc + 2);
        }

        const uint32_t* As = gsm + (kc & 1) * GBUFW;
        const uint32_t* Bs = As + 128 * LDS_S;

        #pragma unroll
        for (int s = 0; s < 4; s++) {
            uint32_t af[4][4];
            #pragma unroll
            for (int i = 0; i < 4; i++) {
                const int base = (wm + i * 16 + g) * LDS_S + s * 8 + tg;
                af[i][0] = As[base];
                af[i][1] = As[base + 8 * LDS_S];
                af[i][2] = As[base + 4];
                af[i][3] = As[base + 8 * LDS_S + 4];
            }
            uint32_t bf[4][2];
            #pragma unroll
            for (int j = 0; j < 4; j++) {
                const int base = (wn + j * 8 + g) * LDS_S + s * 8 + tg;
                bf[j][0] = Bs[base];
                bf[j][1] = Bs[base + 4];
            }
            #pragma unroll
            for (int i = 0; i < 4; i++)
                #pragma unroll
                for (int j = 0; j < 4; j++)
                    mma_tf32(acc[i][j], af[i], bf[j]);
        }
    }

    #pragma unroll
    for (int j = 0; j < 4; j++) {
        const int n = bn0 + wn + j * 8 + 2 * tg;
        const float bx = bias[n], by = bias[n + 1];
        #pragma unroll
        for (int i = 0; i < 4; i++) {
            const int m0 = bm0 + wm + i * 16 + g;
            float2 v0 = make_float2(acc[i][j][0] + bx, acc[i][j][1] + by);
            float2 v1 = make_float2(acc[i][j][2] + bx, acc[i][j][3] + by);
            if (mode < 3) {
                const int h = n >> 6, hd = n & (HD_ - 1);
                const int bb0 = m0 >> 11, t0 = m0 & (T_ - 1);
                const int m1 = m0 + 8;
                const int bb1 = m1 >> 11, t1 = m1 & (T_ - 1);
                *(float2*)&Y[(((size_t)bb0 * H_ + h) * T_ + t0) * HD_ + hd] = v0;
                *(float2*)&Y[(((size_t)bb1 * H_ + h) * T_ + t1) * HD_ + hd] = v1;
            } else {
                *(float2*)&Y[(size_t)m0 * D_ + n] = v0;
                *(float2*)&Y[(size_t)(m0 + 8) * D_ + n] = v1;
            }
        }
    }
}

// Merged QKV launch: blockIdx.z in {0,1,2} selects the projection.
__global__ void __launch_bounds__(256)
gemm_qkv(const float* __restrict__ x,
         const float* __restrict__ Wq, const float* __restrict__ bq,
         const float* __restrict__ Wk, const float* __restrict__ bk,
         const float* __restrict__ Wv, const float* __restrict__ bv)
{
    const int m = blockIdx.z;
    const float* W = (m == 0) ? Wq : (m == 1) ? Wk : Wv;
    const float* b = (m == 0) ? bq : (m == 1) ? bk : bv;
    gemm_body(x, W, b, nullptr, m);
}

__global__ void __launch_bounds__(256)
gemm_out(const float* __restrict__ Wo, const float* __restrict__ bo,
         float* __restrict__ out)
{
    gemm_body(g_o, Wo, bo, out, 3);
}

// ===========================================================================
// Tensor-core flash attention v6 (tf32 mma.sync).
// R15: back to FBr=128 / 256 threads (R14's FBr=64 doubled staging work),
// but __launch_bounds__(256, 2) caps regs at 128 -> 2 CTAs/SM (16 warps):
// one CTA's MMA phase overlaps the other's softmax/MUFU phase.
// No persistent K/V prefetch regs (R7: ~1% value; frees regs for the cap).
// ===========================================================================
constexpr int FBr = 128, FBc = 64;
constexpr int FST_K = 72;                        // Khi row stride (words)
constexpr int FST_V = 68;                        // Vs  row stride (words)
constexpr int KHI_WORDS = 64 * FST_K;            // 4608
constexpr int BUF_WORDS = KHI_WORDS + 64 * FST_V; // 8960 per buffer
constexpr int QST = 65;                          // Q staging stride (buf 1)
constexpr int FLASH_SMEM = 2 * BUF_WORDS * 4;    // 71680 B
constexpr int FTHREADS = 256;

__device__ __forceinline__ int permc(int c) {    // permute col within k8 step
    return ((c & 3) << 1) | (c >> 2);
}

__global__ void __launch_bounds__(FTHREADS, 2)
flash_tc()
{
    extern __shared__ uint32_t smw[];

    const int bh = blockIdx.y;
    const int q0 = blockIdx.x * FBr;
    const float* Qg = g_q + (size_t)bh * T_ * HD_;
    const float* Kg = g_k + (size_t)bh * T_ * HD_;
    const float* Vg = g_v + (size_t)bh * T_ * HD_;

    const int tid = threadIdx.x, lane = tid & 31, wid = tid >> 5;
    const int g = lane >> 2, tg = lane & 3;
    const int wr = wid * 16;                      // wid 0..7 -> rows 0..127

    // K/V staging mapping: rows rr+16i (i=0..3), float4 column cc.
    const int rr = tid >> 4;                      // 0..15
    const int cc = tid & 15;
    const float4* K4 = (const float4*)Kg + cc;
    const float4* V4 = (const float4*)Vg + cc;

    auto stageKV = [&](int bufIdx, int tile) {
        uint32_t* Khi = smw + bufIdx * BUF_WORDS;
        uint32_t* Vs  = Khi + KHI_WORDS;
        const size_t base = (size_t)tile * 64;
        const int dbase = cc * 4;
        #pragma unroll
        for (int i = 0; i < 4; i++) {
            const int r = rr + 16 * i;
            const float4 kv = K4[(base + r) * 16];
            const float kf[4] = {kv.x, kv.y, kv.z, kv.w};
            #pragma unroll
            for (int u = 0; u < 4; u++) {
                const int d = dbase + u;
                Khi[r * FST_K + (d & ~7) + permc(d & 7)] = f2tf32(kf[u]);
            }
        }
        #pragma unroll
        for (int i = 0; i < 4; i++) {
            const int r = rr + 16 * i;
            const float4 vv = V4[(base + r) * 16];
            uint4 vw;
            vw.x = f2tf32(vv.x); vw.y = f2tf32(vv.y);
            vw.z = f2tf32(vv.z); vw.w = f2tf32(vv.w);
            *(uint4*)&Vs[r * FST_V + dbase] = vw;
        }
    };

    // ---- Stage Q (pre-scaled) into buffer-1 region ----
    float* Qst = (float*)(smw + BUF_WORDS);
    #pragma unroll
    for (int i = 0; i < 8; i++) {                 // 128 rows x 16 f4
        const int idx = tid + i * FTHREADS;
        const int r = idx >> 4, qc4 = idx & 15;
        float4 q = *(const float4*)(Qg + (size_t)(q0 + r) * HD_ + qc4 * 4);
        float* d = Qst + r * QST + qc4 * 4;
        d[0] = q.x * 0.125f; d[1] = q.y * 0.125f;
        d[2] = q.z * 0.125f; d[3] = q.w * 0.125f;
    }
    __syncthreads();

    // ---- Extract Q A-fragments (single tf32) ----
    uint32_t qh[8][4];
    #pragma unroll
    for (int s = 0; s < 8; s++) {
        qh[s][0] = f2tf32(Qst[(wr + g)     * QST + s * 8 + tg]);
        qh[s][1] = f2tf32(Qst[(wr + g + 8) * QST + s * 8 + tg]);
        qh[s][2] = f2tf32(Qst[(wr + g)     * QST + s * 8 + tg + 4]);
        qh[s][3] = f2tf32(Qst[(wr + g + 8) * QST + s * 8 + tg + 4]);
    }
    __syncthreads();   // Q reads done before buffer-1 staging overwrites

    // ---- Stage tile 0 into buffer 0 ----
    stageKV(0, 0);

    float o[8][4];
    #pragma unroll
    for (int j = 0; j < 8; j++)
        #pragma unroll
        for (int r = 0; r < 4; r++) o[j][r] = 0.f;
    float m0 = -1e30f, m1 = -1e30f, l0 = 0.f, l1 = 0.f;

    constexpr int NT = T_ / FBc;                  // 32
    for (int it = 0; it < NT; it++) {
        // Orders: staging of buf[it&1] visible; prev-iter reads of
        // buf[(it+1)&1] complete before restaging it.
        __syncthreads();

        if (it + 1 < NT) stageKV((it + 1) & 1, it + 1);

        const uint32_t* buf = smw + (it & 1) * BUF_WORDS;
        const uint32_t* Khi = buf;
        const uint32_t* Vs  = buf + KHI_WORDS;

        // ---- S = Q @ K^T (single tf32) ----
        float sacc[8][4];
        #pragma unroll
        for (int j = 0; j < 8; j++)
            #pragma unroll
            for (int r = 0; r < 4; r++) sacc[j][r] = 0.f;

        #pragma unroll
        for (int s = 0; s < 8; s++) {
            #pragma unroll
            for (int jt = 0; jt < 8; jt++) {
                const uint2 kh2 = *(const uint2*)&Khi[(jt * 8 + g) * FST_K + s * 8 + 2 * tg];
                const uint32_t bhh[2] = {kh2.x, kh2.y};
                mma_tf32(sacc[jt], qh[s], bhh);
            }
        }

        // ---- Online softmax (rows g and g+8); e's stay in sacc regs ----
        float mx0 = -1e30f, mx1 = -1e30f;
        #pragma unroll
        for (int jt = 0; jt < 8; jt++) {
            mx0 = fmaxf(mx0, fmaxf(sacc[jt][0], sacc[jt][1]));
            mx1 = fmaxf(mx1, fmaxf(sacc[jt][2], sacc[jt][3]));
        }
        mx0 = fmaxf(mx0, __shfl_xor_sync(0xffffffffu, mx0, 1));
        mx0 = fmaxf(mx0, __shfl_xor_sync(0xffffffffu, mx0, 2));
        mx1 = fmaxf(mx1, __shfl_xor_sync(0xffffffffu, mx1, 1));
        mx1 = fmaxf(mx1, __shfl_xor_sync(0xffffffffu, mx1, 2));

        const float mn0 = fmaxf(m0, mx0), mn1 = fmaxf(m1, mx1);
        const float a0 = __expf(m0 - mn0), a1 = __expf(m1 - mn1);

        float rs0 = 0.f, rs1 = 0.f;
        #pragma unroll
        for (int jt = 0; jt < 8; jt++) {
            sacc[jt][0] = __expf(sacc[jt][0] - mn0);
            sacc[jt][1] = __expf(sacc[jt][1] - mn0);
            sacc[jt][2] = __expf(sacc[jt][2] - mn1);
            sacc[jt][3] = __expf(sacc[jt][3] - mn1);
            rs0 += sacc[jt][0] + sacc[jt][1];
            rs1 += sacc[jt][2] + sacc[jt][3];
        }
        rs0 += __shfl_xor_sync(0xffffffffu, rs0, 1);
        rs0 += __shfl_xor_sync(0xffffffffu, rs0, 2);
        rs1 += __shfl_xor_sync(0xffffffffu, rs1, 1);
        rs1 += __shfl_xor_sync(0xffffffffu, rs1, 2);

        l0 = l0 * a0 + rs0;
        l1 = l1 * a1 + rs1;
        m0 = mn0; m1 = mn1;
        #pragma unroll
        for (int jt = 0; jt < 8; jt++) {
            o[jt][0] *= a0; o[jt][1] *= a0;
            o[jt][2] *= a1; o[jt][3] *= a1;
        }

        // ---- O += P @ V : P direct from registers (permuted key slots) ----
        #pragma unroll
        for (int jt = 0; jt < 8; jt++) {
            const uint32_t pa[4] = {f2tf32(sacc[jt][0]), f2tf32(sacc[jt][2]),
                                    f2tf32(sacc[jt][1]), f2tf32(sacc[jt][3])};
            const uint32_t* v0row = &Vs[(jt * 8 + 2 * tg)     * FST_V + g];
            const uint32_t* v1row = &Vs[(jt * 8 + 2 * tg + 1) * FST_V + g];
            #pragma unroll
            for (int dt = 0; dt < 8; dt++) {
                const uint32_t vb[2] = {v0row[dt * 8], v1row[dt * 8]};
                mma_tf32(o[dt], pa, vb);
            }
        }
    }

    // ---- Epilogue: normalize, write to [B, T, H*HD] ----
    const float i0 = 1.0f / l0, i1 = 1.0f / l1;
    const int bb = bh >> 4, h = bh & 15;
    const int row0 = q0 + wr + g, row1 = row0 + 8;
    #pragma unroll
    for (int dt = 0; dt < 8; dt++) {
        const int dcol = h * HD_ + dt * 8 + 2 * tg;
        *(float2*)&g_o[((size_t)bb * T_ + row0) * D_ + dcol] =
            make_float2(o[dt][0] * i0, o[dt][1] * i0);
        *(float2*)&g_o[((size_t)bb * T_ + row1) * D_ + dcol] =
            make_float2(o[dt][2] * i1, o[dt][3] * i1);
    }
}

// ---------------------------------------------------------------------------
extern "C" void kernel_launch(void* const* d_in, const int* in_sizes, int n_in,
                              void* d_out, int out_size)
{
    const float* x  = (const float*)d_in[0];
    const float* Wq = (const float*)d_in[1];
    const float* bq = (const float*)d_in[2];
    const float* Wk = (const float*)d_in[3];
    const float* bk = (const float*)d_in[4];
    const float* Wv = (const float*)d_in[5];
    const float* bv = (const float*)d_in[6];
    const float* Wo = (const float*)d_in[7];
    const float* bo = (const float*)d_in[8];
    float* out = (float*)d_out;

    cudaFuncSetAttribute(gemm_qkv, cudaFuncAttributeMaxDynamicSharedMemorySize,
                         GEMM_SMEM);
    cudaFuncSetAttribute(gemm_out, cudaFuncAttributeMaxDynamicSharedMemorySize,
                         GEMM_SMEM);
    cudaFuncSetAttribute(flash_tc, cudaFuncAttributeMaxDynamicSharedMemorySize,
                         FLASH_SMEM);

    dim3 gq(D_ / 128, MROWS / 128, 3);       // (8, 64, 3) merged QKV
    gemm_qkv<<<gq, 256, GEMM_SMEM>>>(x, Wq, bq, Wk, bk, Wv, bv);

    dim3 attn_grid(T_ / FBr, B_ * H_);       // (16, 64): x=qtile, y=bh
    flash_tc<<<attn_grid, FTHREADS, FLASH_SMEM>>>();

    dim3 gg(D_ / 128, MROWS / 128);          // (8, 64)
    gemm_out<<<gg, 256, GEMM_SMEM>>>(Wo, bo, out);
}